// round 1
// baseline (speedup 1.0000x reference)
#include <cuda_runtime.h>
#include <math.h>

// Problem constants
#define B_ 1024
#define I_ 256
#define O_ 256
#define K_ 128

// Tiling
#define O_TILE 8     // outputs per CTA
#define B_TILE 256   // batches per CTA (== blockDim.x)
#define ICH 8        // i-chunk staged in SMEM per iteration
#define RSTR 10      // padded smem row stride (floats) for 8 o's -> 2-way STS conflicts, even offsets for LDS.64

// Per-(b,i) precomputed activation data, stored transposed [i][b] for coalesced reads.
//  .x = silu(tanh(x))   .y = scaled bin coordinate in [0,127]
__device__ float2 g_prep[I_ * B_];

__global__ __launch_bounds__(256) void prep_kernel(const float* __restrict__ x) {
    int idx = blockIdx.x * blockDim.x + threadIdx.x;
    if (idx >= B_ * I_) return;
    int b = idx / I_;
    int i = idx % I_;
    float p = tanhf(x[idx]);                   // p in [-1, 1] => clip is identity
    float act = p / (1.0f + expf(-p));         // silu(p)
    float scaled = (p + 1.0f) * 63.5f;         // (p - DMIN) / step, step = 2/127
    g_prep[i * B_ + b] = make_float2(act, scaled);
}

__global__ __launch_bounds__(256) void kan_kernel(
    const float* __restrict__ bw,     // [O, I]
    const float* __restrict__ coeff,  // [O, I, K]
    const float* __restrict__ scale,  // [O, I]
    const float* __restrict__ bias,   // [O]
    float* __restrict__ out)          // [B, O]
{
    // Transposed coefficient tile: sC[(ic*K + k)*RSTR + o], o in [0, O_TILE)
    __shared__ __align__(16) float sC[ICH * K_ * RSTR];   // 40 KB
    __shared__ __align__(16) float sW[ICH][O_TILE];       // base weights slice

    const int o0 = blockIdx.x * O_TILE;
    const int b  = blockIdx.y * B_TILE + threadIdx.x;

    float acc[O_TILE];
#pragma unroll
    for (int o = 0; o < O_TILE; o++) acc[o] = 0.0f;

    for (int i0 = 0; i0 < I_; i0 += ICH) {
        __syncthreads();  // previous iteration's reads done before overwrite

        // Prefetch per-(b,i) activation data for this chunk (hides LDG latency behind staging)
        float2 pv[ICH];
#pragma unroll
        for (int ic = 0; ic < ICH; ic++)
            pv[ic] = g_prep[(i0 + ic) * B_ + b];

        // Stage base-weight slice
        if (threadIdx.x < ICH * O_TILE) {
            int ic = threadIdx.x >> 3;
            int o  = threadIdx.x & 7;
            sW[ic][o] = bw[(o0 + o) * I_ + (i0 + ic)];
        }

        // Stage coefficient tile (coalesced global reads; stride-RSTR scattered STS, 2-way conflicts)
#pragma unroll 4
        for (int j = 0; j < (O_TILE * ICH * K_) / 256; j++) {
            int lin = j * 256 + threadIdx.x;
            int o  = lin >> 10;        // / (ICH*K_)
            int r  = lin & 1023;
            int ic = r >> 7;           // / K_
            int k  = r & 127;
            float v = coeff[(size_t)(o0 + o) * (I_ * K_) + (i0 + ic) * K_ + k]
                    * scale[(o0 + o) * I_ + (i0 + ic)];
            sC[(ic * K_ + k) * RSTR + o] = v;
        }
        __syncthreads();

        // Main accumulation: each thread = one batch b, O_TILE outputs
#pragma unroll
        for (int ic = 0; ic < ICH; ic++) {
            float act    = pv[ic].x;
            float scaled = pv[ic].y;
            int   l    = min((int)scaled, K_ - 1);     // scaled >= 0 always
            float frac = scaled - (float)l;
            float wl   = 1.0f - frac;
            int   rr   = min(l + 1, K_ - 1);
            const float* rowL = &sC[(ic * K_ + l)  * RSTR];
            const float* rowR = &sC[(ic * K_ + rr) * RSTR];
#pragma unroll
            for (int q = 0; q < O_TILE / 2; q++) {
                float2 cl = *reinterpret_cast<const float2*>(rowL + 2 * q);
                float2 cr = *reinterpret_cast<const float2*>(rowR + 2 * q);
                float2 wv = *reinterpret_cast<const float2*>(&sW[ic][2 * q]);
                acc[2 * q]     += wl * cl.x + frac * cr.x + act * wv.x;
                acc[2 * q + 1] += wl * cl.y + frac * cr.y + act * wv.y;
            }
        }
    }

    // Epilogue: bias + store (two 16B stores per thread, each a fully-covered 32B sector)
#pragma unroll
    for (int o = 0; o < O_TILE; o += 4) {
        float4 r;
        r.x = acc[o + 0] + bias[o0 + o + 0];
        r.y = acc[o + 1] + bias[o0 + o + 1];
        r.z = acc[o + 2] + bias[o0 + o + 2];
        r.w = acc[o + 3] + bias[o0 + o + 3];
        *reinterpret_cast<float4*>(&out[(size_t)b * O_ + o0 + o]) = r;
    }
}

extern "C" void kernel_launch(void* const* d_in, const int* in_sizes, int n_in,
                              void* d_out, int out_size) {
    const float* x     = (const float*)d_in[0];
    const float* bw    = (const float*)d_in[1];
    const float* coeff = (const float*)d_in[2];
    const float* scale = (const float*)d_in[3];
    const float* bias  = (const float*)d_in[4];
    float* out = (float*)d_out;

    prep_kernel<<<(B_ * I_) / 256, 256>>>(x);

    dim3 grid(O_ / O_TILE, B_ / B_TILE);   // 32 x 4 = 128 CTAs
    kan_kernel<<<grid, 256>>>(bw, coeff, scale, bias, out);
}

// round 2
// speedup vs baseline: 1.0866x; 1.0866x over previous
#include <cuda_runtime.h>
#include <math.h>

// Problem constants
#define B_ 1024
#define I_ 256
#define O_ 256
#define K_ 128

// Tiling
#define OT 32                 // outputs per CTA (lane = o)
#define BT 256                // batches per CTA
#define NSEG 16               // i-segments (grid.z)
#define ISEG (I_ / NSEG)      // 16 i per CTA
#define ICH 2                 // i staged per chunk
#define NCHUNK (ISEG / ICH)   // 8
#define RS (K_ + 1)           // smem row stride 129 floats -> gather banks (lane+l)%32, conflict-free

// Precomputed per-(b,i) activation data, transposed [i][b]:
//  g_prep.x = silu(tanh(x)), g_prep.y = frac;  g_lidx = left knot index (0..127)
__device__ float2 g_prep[I_ * B_];
__device__ unsigned char g_lidx[I_ * B_];
// Partial sums, one exclusive slice per i-segment (deterministic, no atomics)
__device__ float g_part[NSEG][B_][O_];

__global__ __launch_bounds__(256) void prep_kernel(const float* __restrict__ x) {
    int idx = blockIdx.x * 256 + threadIdx.x;
    int b = idx / I_;
    int i = idx % I_;
    float p = tanhf(x[idx]);                        // p in [-1,1] => clip identity
    float act = p / (1.0f + expf(-p));              // silu(p)
    float scaled = fminf(fmaxf((p + 1.0f) * 63.5f, 0.0f), 127.0f);
    int l = (int)scaled;                            // 0..127
    float frac = scaled - (float)l;
    g_prep[i * B_ + b] = make_float2(act, frac);
    g_lidx[i * B_ + b] = (unsigned char)l;
}

__global__ __launch_bounds__(256, 4) void kan_main(
    const float* __restrict__ bw,     // [O, I]
    const float* __restrict__ coeff,  // [O, I, K]
    const float* __restrict__ scale)  // [O, I]
{
    __shared__ __align__(16) float  sC[ICH * OT * RS];  // 33 KB: [ic][o][K+1], pad zeroed
    __shared__ __align__(16) float2 sP[ICH][BT];        // 4 KB  (act, frac)
    __shared__ unsigned char        sL[ICH][BT];        // 512 B (left index)
    __shared__ float                sW[ICH][OT];        // base-weight slice

    const int lane = threadIdx.x & 31;
    const int warp = threadIdx.x >> 5;
    const int o0 = blockIdx.x * OT;
    const int b0 = blockIdx.y * BT;
    const int i0seg = blockIdx.z * ISEG;
    const int o = o0 + lane;

    float acc[32];
#pragma unroll
    for (int j = 0; j < 32; j++) acc[j] = 0.0f;

    for (int c = 0; c < NCHUNK; c++) {
        const int i0 = i0seg + c * ICH;
        __syncthreads();  // previous chunk's reads complete before overwrite

        // Stage per-(b,i) scalars (coalesced)
#pragma unroll
        for (int ic = 0; ic < ICH; ic++) {
            sP[ic][threadIdx.x] = g_prep[(i0 + ic) * B_ + b0 + threadIdx.x];
            sL[ic][threadIdx.x] = g_lidx[(i0 + ic) * B_ + b0 + threadIdx.x];
        }
        // Stage base-weight slice
        if (threadIdx.x < ICH * OT) {
            int ic = threadIdx.x >> 5, oo = threadIdx.x & 31;
            sW[ic][oo] = bw[(size_t)(o0 + oo) * I_ + (i0 + ic)];
        }
        // Stage coefficient rows: one (o,ic) row of K=128 per warp-iteration (coalesced LDG.128)
        for (int t = warp; t < ICH * OT; t += 8) {
            int ic = t >> 5, oo = t & 31;
            const float* src = coeff + ((size_t)(o0 + oo) * I_ + (i0 + ic)) * (size_t)K_;
            float s = scale[(size_t)(o0 + oo) * I_ + (i0 + ic)];
            float4 v = reinterpret_cast<const float4*>(src)[lane];
            float* dst = &sC[(ic * OT + oo) * RS + 4 * lane];
            dst[0] = v.x * s; dst[1] = v.y * s; dst[2] = v.z * s; dst[3] = v.w * s;
            if (lane == 0) sC[(ic * OT + oo) * RS + K_] = 0.0f;  // pad: l=127 reads it with frac=0
        }
        __syncthreads();

        // Per-lane row pointers and weights for this chunk
        const float* row0 = &sC[(0 * OT + lane) * RS];
        const float* row1 = &sC[(1 * OT + lane) * RS];
        float w0 = sW[0][lane];
        float w1 = sW[1][lane];

        // Hot loop: warp-uniform l/frac, conflict-free consecutive-lane gathers
#pragma unroll
        for (int bb = 0; bb < 32; bb++) {
            const int bl = warp * 32 + bb;
            {
                float2 pv = sP[0][bl];
                int l = sL[0][bl];
                float cl = row0[l], cr = row0[l + 1];
                acc[bb] = fmaf(1.0f - pv.y, cl, acc[bb]);
                acc[bb] = fmaf(pv.y, cr, acc[bb]);
                acc[bb] = fmaf(pv.x, w0, acc[bb]);
            }
            {
                float2 pv = sP[1][bl];
                int l = sL[1][bl];
                float cl = row1[l], cr = row1[l + 1];
                acc[bb] = fmaf(1.0f - pv.y, cl, acc[bb]);
                acc[bb] = fmaf(pv.y, cr, acc[bb]);
                acc[bb] = fmaf(pv.x, w1, acc[bb]);
            }
        }
    }

    // Write exclusive partial slice (coalesced 128B per bb)
#pragma unroll 4
    for (int bb = 0; bb < 32; bb++)
        g_part[blockIdx.z][b0 + warp * 32 + bb][o] = acc[bb];
}

__global__ __launch_bounds__(256) void kan_reduce(
    const float* __restrict__ bias, float* __restrict__ out) {
    int t = blockIdx.x * 256 + threadIdx.x;  // 0..65535, one float4 of out each
    int b = t >> 6;                          // O/4 = 64 float4 per row
    int oq = t & 63;
    float4 s = reinterpret_cast<const float4*>(&g_part[0][b][0])[oq];
#pragma unroll
    for (int seg = 1; seg < NSEG; seg++) {
        float4 v = reinterpret_cast<const float4*>(&g_part[seg][b][0])[oq];
        s.x += v.x; s.y += v.y; s.z += v.z; s.w += v.w;
    }
    float4 bi = reinterpret_cast<const float4*>(bias)[oq];
    s.x += bi.x; s.y += bi.y; s.z += bi.z; s.w += bi.w;
    reinterpret_cast<float4*>(out)[t] = s;
}

extern "C" void kernel_launch(void* const* d_in, const int* in_sizes, int n_in,
                              void* d_out, int out_size) {
    const float* x     = (const float*)d_in[0];
    const float* bw    = (const float*)d_in[1];
    const float* coeff = (const float*)d_in[2];
    const float* scale = (const float*)d_in[3];
    const float* bias  = (const float*)d_in[4];
    float* out = (float*)d_out;

    prep_kernel<<<(B_ * I_) / 256, 256>>>(x);

    dim3 grid(O_ / OT, B_ / BT, NSEG);  // 8 x 4 x 16 = 512 CTAs
    kan_main<<<grid, 256>>>(bw, coeff, scale);

    kan_reduce<<<(B_ * O_ / 4) / 256, 256>>>(bias, out);
}

// round 3
// speedup vs baseline: 1.3970x; 1.2857x over previous
#include <cuda_runtime.h>
#include <math.h>

// Problem constants
#define B_ 1024
#define I_ 256
#define O_ 256
#define K_ 128

// Tiling
#define OT 32        // outputs per CTA (lane = o)
#define BT 256       // batches per CTA
#define NSEG 16      // i-segments (grid.z)
#define ISEG (I_ / NSEG)
#define NW 16        // warps per CTA (512 threads)
#define BPW (BT / NW) // 16 batches per warp -> acc[16]
#define RSP 129      // smem row stride in float2: gather pair-bank = (lane + l) % 16, conflict-free

// Per-(b,i) packed activation data [i][b]:
//  .x = silu(tanh(x))  .y = 1-frac  .z = frac  .w = bitcast(l*8) byte offset into pair row
__device__ float4 g_pack[I_ * B_];
// Exclusive partial sums per i-segment (deterministic, no atomics)
__device__ float g_part[NSEG][B_][O_];

__global__ __launch_bounds__(256) void prep_kernel(const float* __restrict__ x) {
    int idx = blockIdx.x * 256 + threadIdx.x;   // idx = b*I + i (coalesced read)
    int b = idx / I_;
    int i = idx % I_;
    float xv = x[idx];
    // tanh via exp (accurate ~1e-7; tanh.approx's 2^-11 error is too big for the bins)
    float ax = fabsf(xv);
    float e  = __expf(-2.0f * ax);
    float r  = (1.0f - e) / (1.0f + e);
    float p  = copysignf(r, xv);                // tanh(x), in [-1,1] => clip identity
    float sg = 1.0f / (1.0f + __expf(-p));
    float act = p * sg;                          // silu(p)
    float scaled = fminf(fmaxf((p + 1.0f) * 63.5f, 0.0f), 127.0f);
    int   l    = (int)scaled;                    // 0..127
    float frac = scaled - (float)l;
    g_pack[i * B_ + b] = make_float4(act, 1.0f - frac, frac, __int_as_float(l * 8));
}

__global__ __launch_bounds__(512, 2) void kan_main(
    const float* __restrict__ bw,     // [O, I]
    const float* __restrict__ coeff,  // [O, I, K]
    const float* __restrict__ scale)  // [O, I]
{
    __shared__ __align__(16) float2 sC[OT * RSP];  // 33 KB: [o][k] = (c_k, c_{k+1}) scaled
    __shared__ __align__(16) float4 sPk[BT];       // 4 KB packed per-(b,i) scalars
    __shared__ float sW[OT];                       // base-weight column

    const int lane = threadIdx.x & 31;
    const int warp = threadIdx.x >> 5;             // 0..15
    const int o0 = blockIdx.x * OT;
    const int b0 = blockIdx.y * BT;
    const int i0 = blockIdx.z * ISEG;

    float acc[BPW];
#pragma unroll
    for (int j = 0; j < BPW; j++) acc[j] = 0.0f;

    for (int ii = 0; ii < ISEG; ii++) {
        const int i = i0 + ii;
        __syncthreads();  // previous iteration's reads complete

        // Stage packed scalars (threads 0..255) and base weights (256..287)
        if (threadIdx.x < BT)
            sPk[threadIdx.x] = g_pack[i * B_ + b0 + threadIdx.x];
        else if (threadIdx.x < BT + OT)
            sW[threadIdx.x - BT] = bw[(size_t)(o0 + threadIdx.x - BT) * I_ + i];

        // Stage coefficient pair rows: 32 rows / 16 warps = 2 per warp.
        // lane handles k = lane + 32j: pair (c_k*s, c_{k+1}*s); STS.64 conflict-free.
        for (int t = warp; t < OT; t += NW) {
            const float* src = coeff + ((size_t)(o0 + t) * I_ + i) * (size_t)K_;
            float s = scale[(size_t)(o0 + t) * I_ + i];
            float v0 = src[lane], v1 = src[lane + 32], v2 = src[lane + 64], v3 = src[lane + 96];
            float n0 = __shfl_down_sync(0xffffffffu, v0, 1);
            float n1 = __shfl_down_sync(0xffffffffu, v1, 1);
            float n2 = __shfl_down_sync(0xffffffffu, v2, 1);
            float n3 = __shfl_down_sync(0xffffffffu, v3, 1);
            if (lane == 31) {           // lane31's successor lives in the next group
                n0 = __shfl_sync(0xffffffffu, v1, 0);
                n1 = __shfl_sync(0xffffffffu, v2, 0);
                n2 = __shfl_sync(0xffffffffu, v3, 0);
                n3 = 0.0f;              // c[128] pad: l=127 has frac==0
            } else {
                __shfl_sync(0xffffffffu, v1, 0);  // keep shuffle participation uniform
                __shfl_sync(0xffffffffu, v2, 0);
                __shfl_sync(0xffffffffu, v3, 0);
            }
            float2* row = &sC[t * RSP];
            row[lane]      = make_float2(v0 * s, n0 * s);
            row[lane + 32] = make_float2(v1 * s, n1 * s);
            row[lane + 64] = make_float2(v2 * s, n2 * s);
            row[lane + 96] = make_float2(v3 * s, n3 * s);
        }
        __syncthreads();

        const float w = sW[lane];
        const char* rowb = (const char*)&sC[lane * RSP];  // lane's pair row (8B aligned)

        // Hot loop: 1 bcast LDS.128 + 1 gather LDS.64 + 3 FFMA per (b,i)
#pragma unroll
        for (int bb = 0; bb < BPW; bb++) {
            float4 pk = sPk[warp * BPW + bb];
            float2 c = *(const float2*)(rowb + __float_as_int(pk.w));
            acc[bb] = fmaf(pk.y, c.x, acc[bb]);   // (1-frac) * c_l
            acc[bb] = fmaf(pk.z, c.y, acc[bb]);   // frac * c_r
            acc[bb] = fmaf(pk.x, w, acc[bb]);     // silu * base_weight
        }
    }

    // Exclusive partial slice (coalesced 128B rows)
#pragma unroll
    for (int bb = 0; bb < BPW; bb++)
        g_part[blockIdx.z][b0 + warp * BPW + bb][o0 + lane] = acc[bb];
}

__global__ __launch_bounds__(256) void kan_reduce(
    const float* __restrict__ bias, float* __restrict__ out) {
    int t = blockIdx.x * 256 + threadIdx.x;  // one float4 of out each
    int b = t >> 6;
    int oq = t & 63;
    float4 s = reinterpret_cast<const float4*>(&g_part[0][b][0])[oq];
#pragma unroll
    for (int seg = 1; seg < NSEG; seg++) {
        float4 v = reinterpret_cast<const float4*>(&g_part[seg][b][0])[oq];
        s.x += v.x; s.y += v.y; s.z += v.z; s.w += v.w;
    }
    float4 bi = reinterpret_cast<const float4*>(bias)[oq];
    s.x += bi.x; s.y += bi.y; s.z += bi.z; s.w += bi.w;
    reinterpret_cast<float4*>(out)[t] = s;
}

extern "C" void kernel_launch(void* const* d_in, const int* in_sizes, int n_in,
                              void* d_out, int out_size) {
    const float* x     = (const float*)d_in[0];
    const float* bw    = (const float*)d_in[1];
    const float* coeff = (const float*)d_in[2];
    const float* scale = (const float*)d_in[3];
    const float* bias  = (const float*)d_in[4];
    float* out = (float*)d_out;

    prep_kernel<<<(B_ * I_) / 256, 256>>>(x);

    dim3 grid(O_ / OT, B_ / BT, NSEG);  // 8 x 4 x 16 = 512 CTAs
    kan_main<<<grid, 512>>>(bw, coeff, scale);

    kan_reduce<<<(B_ * O_ / 4) / 256, 256>>>(bias, out);
}

// round 5
// speedup vs baseline: 2.2967x; 1.6440x over previous
#include <cuda_runtime.h>
#include <math.h>

// Problem constants
#define B_ 1024
#define I_ 256
#define O_ 256
#define K_ 128

// Tiling
#define OT 32         // outputs per CTA (lane = o)
#define BT 256        // batches per CTA
#define NSEG 16       // i-segments (grid.z)
#define ISEG (I_ / NSEG)
#define NW 16         // warps per CTA (512 threads)
#define BPW (BT / NW) // 16 batches per warp
#define RS 129        // row stride (floats), odd -> gather bank (lane+l)%32 conflict-free

// Per-(b,i) packed activation data [i][b]:
//  .x = silu(tanh(x))  .y = 1-frac  .z = frac  .w = bitcast(l*4) byte offset into row
__device__ float4 g_pack[I_ * B_];
// Exclusive partial sums per i-segment (deterministic, no atomics)
__device__ float g_part[NSEG][B_][O_];

__global__ __launch_bounds__(256) void prep_kernel(const float* __restrict__ x) {
    int idx = blockIdx.x * 256 + threadIdx.x;
    int b = idx / I_;
    int i = idx % I_;
    float xv = x[idx];
    float ax = fabsf(xv);
    float e  = __expf(-2.0f * ax);
    float r  = (1.0f - e) / (1.0f + e);
    float p  = copysignf(r, xv);                 // tanh(x) in [-1,1] => clip identity
    float sg = 1.0f / (1.0f + __expf(-p));
    float act = p * sg;                           // silu(p)
    float scaled = fminf(fmaxf((p + 1.0f) * 63.5f, 0.0f), 127.0f);
    int   l    = (int)scaled;                     // 0..127
    float frac = scaled - (float)l;
    g_pack[i * B_ + b] = make_float4(act, 1.0f - frac, frac, __int_as_float(l * 4));
}

__global__ __launch_bounds__(512, 2) void kan_main(
    const float* __restrict__ bw,     // [O, I]
    const float* __restrict__ coeff,  // [O, I, K]
    const float* __restrict__ scale)  // [O, I]
{
    __shared__ float sC[2][OT * RS];               // 2 x 16.1 KB, [o][k] scaled, +pad
    __shared__ __align__(16) float4 sPk[2][BT];    // 2 x 4 KB
    __shared__ float sW[ISEG][OT];                 // 2 KB base-weight slice (whole segment)

    const int lane = threadIdx.x & 31;
    const int warp = threadIdx.x >> 5;             // 0..15
    const int o0 = blockIdx.x * OT;
    const int b0 = blockIdx.y * BT;
    const int i0 = blockIdx.z * ISEG;
    const int r0 = warp * 2;                       // this warp's two coefficient rows
    const int r1 = warp * 2 + 1;

    // One-time preload of the base-weight slice for the whole segment
    for (int t = threadIdx.x; t < ISEG * OT; t += 512) {
        int oo = t >> 4, ii = t & 15;
        sW[ii][oo] = bw[(size_t)(o0 + oo) * I_ + i0 + ii];
    }

    float acc[BPW];
#pragma unroll
    for (int j = 0; j < BPW; j++) acc[j] = 0.0f;

    // Register prefetch buffers
    float va[2][4], sc[2];
    float4 pkreg;

    // Prologue: fetch iteration 0
    {
        const float* s0 = coeff + ((size_t)(o0 + r0) * I_ + i0) * (size_t)K_;
        const float* s1 = coeff + ((size_t)(o0 + r1) * I_ + i0) * (size_t)K_;
        va[0][0] = s0[lane]; va[0][1] = s0[lane + 32]; va[0][2] = s0[lane + 64]; va[0][3] = s0[lane + 96];
        va[1][0] = s1[lane]; va[1][1] = s1[lane + 32]; va[1][2] = s1[lane + 64]; va[1][3] = s1[lane + 96];
        sc[0] = scale[(size_t)(o0 + r0) * I_ + i0];
        sc[1] = scale[(size_t)(o0 + r1) * I_ + i0];
        if (threadIdx.x < BT) pkreg = g_pack[(size_t)i0 * B_ + b0 + threadIdx.x];
    }

    for (int ii = 0; ii < ISEG; ii++) {
        const int buf = ii & 1;

        // STS phase: commit prefetched regs to this buffer (conflict-free STS.32)
        {
            float* row0 = &sC[buf][r0 * RS];
            float* row1 = &sC[buf][r1 * RS];
            row0[lane]      = va[0][0] * sc[0];
            row0[lane + 32] = va[0][1] * sc[0];
            row0[lane + 64] = va[0][2] * sc[0];
            row0[lane + 96] = va[0][3] * sc[0];
            row1[lane]      = va[1][0] * sc[1];
            row1[lane + 32] = va[1][1] * sc[1];
            row1[lane + 64] = va[1][2] * sc[1];
            row1[lane + 96] = va[1][3] * sc[1];
            if (lane == 0) { row0[K_] = 0.0f; row1[K_] = 0.0f; }  // pad (l=127 reads it, frac=0)
            if (threadIdx.x < BT) sPk[buf][threadIdx.x] = pkreg;
        }

        // Fetch phase: issue next iteration's LDGs (latency hidden behind hot loop)
        if (ii + 1 < ISEG) {
            const int inx = i0 + ii + 1;
            const float* s0 = coeff + ((size_t)(o0 + r0) * I_ + inx) * (size_t)K_;
            const float* s1 = coeff + ((size_t)(o0 + r1) * I_ + inx) * (size_t)K_;
            va[0][0] = s0[lane]; va[0][1] = s0[lane + 32]; va[0][2] = s0[lane + 64]; va[0][3] = s0[lane + 96];
            va[1][0] = s1[lane]; va[1][1] = s1[lane + 32]; va[1][2] = s1[lane + 64]; va[1][3] = s1[lane + 96];
            sc[0] = scale[(size_t)(o0 + r0) * I_ + inx];
            sc[1] = scale[(size_t)(o0 + r1) * I_ + inx];
            if (threadIdx.x < BT) pkreg = g_pack[(size_t)inx * B_ + b0 + threadIdx.x];
        }

        __syncthreads();  // buffer 'buf' fully staged; previous buffer free for next STS

        // Hot loop: per (b,i): 1 bcast LDS.128 + 2 conflict-free LDS.32 + 3 FFMA
        const float w = sW[ii][lane];
        const char* rowb = (const char*)&sC[buf][lane * RS];
        const float4* pkp = &sPk[buf][warp * BPW];
#pragma unroll
        for (int bb = 0; bb < BPW; bb++) {
            float4 pk = pkp[bb];
            int off = __float_as_int(pk.w);
            float cl = *(const float*)(rowb + off);
            float cr = *(const float*)(rowb + off + 4);
            acc[bb] = fmaf(pk.y, cl, acc[bb]);   // (1-frac) * c_l
            acc[bb] = fmaf(pk.z, cr, acc[bb]);   // frac * c_r
            acc[bb] = fmaf(pk.x, w, acc[bb]);    // silu * base_weight
        }
    }

    // Exclusive partial slice (coalesced 128B rows)
#pragma unroll
    for (int bb = 0; bb < BPW; bb++)
        g_part[blockIdx.z][b0 + warp * BPW + bb][o0 + lane] = acc[bb];
}

__global__ __launch_bounds__(256) void kan_reduce(
    const float* __restrict__ bias, float* __restrict__ out) {
    int t = blockIdx.x * 256 + threadIdx.x;  // one float4 of out each
    int b = t >> 6;
    int oq = t & 63;
    float4 s = reinterpret_cast<const float4*>(&g_part[0][b][0])[oq];
#pragma unroll
    for (int seg = 1; seg < NSEG; seg++) {
        float4 v = reinterpret_cast<const float4*>(&g_part[seg][b][0])[oq];
        s.x += v.x; s.y += v.y; s.z += v.z; s.w += v.w;
    }
    float4 bi = reinterpret_cast<const float4*>(bias)[oq];
    s.x += bi.x; s.y += bi.y; s.z += bi.z; s.w += bi.w;
    reinterpret_cast<float4*>(out)[t] = s;
}

extern "C" void kernel_launch(void* const* d_in, const int* in_sizes, int n_in,
                              void* d_out, int out_size) {
    const float* x     = (const float*)d_in[0];
    const float* bw    = (const float*)d_in[1];
    const float* coeff = (const float*)d_in[2];
    const float* scale = (const float*)d_in[3];
    const float* bias  = (const float*)d_in[4];
    float* out = (float*)d_out;

    prep_kernel<<<(B_ * I_) / 256, 256>>>(x);

    dim3 grid(O_ / OT, B_ / BT, NSEG);  // 8 x 4 x 16 = 512 CTAs
    kan_main<<<grid, 512>>>(bw, coeff, scale);

    kan_reduce<<<(B_ * O_ / 4) / 256, 256>>>(bias, out);
}